// round 11
// baseline (speedup 1.0000x reference)
#include <cuda_runtime.h>
#include <math.h>

// ---------------------------------------------------------------------------
// BFM factorization-machine scoring, sparsity-aware, single fused kernel with
// a dedicated streaming-consumer block.
//   y = w0 + x.w_bias + u.t + t.b + 0.5*(b.b - sum_b_sq) + u.b
//   out = sigmoid(y * delta)
// 591 producer blocks scan x (2 float4/thread) and publish packed (idx,val)
// pairs via atomicExch; bias accumulates via rare scalar atomics. Block
// gridDim-1 is a consumer: its 8 thread-groups poll the pair list and gather
// embedding rows WHILE the scan is still running, so the post-scan tail is
// only the last few entries + a 2-barrier reduction.
// ---------------------------------------------------------------------------

#define KDIM 64
#define TPB  512
#define CTAS_PER_SM 4
#define NSM  148
#define PAIR_CAP 4096

__device__ int                g_nnz  = 0;
__device__ int                g_done = 0;
__device__ float              g_bias = 0.f;
__device__ unsigned long long g_pair[PAIR_CAP];   // (idx<<32)|bits(val); 0 = empty

__device__ __forceinline__ void emit_nz(int idx, float v, const float* __restrict__ wb)
{
    int p = atomicAdd(&g_nnz, 1);
    unsigned long long packed =
        ((unsigned long long)(unsigned int)idx << 32) | (unsigned long long)__float_as_uint(v);
    atomicExch(&g_pair[p], packed);               // strong write, poll-visible
    atomicAdd(&g_bias, v * __ldg(wb + idx));
}

__global__ void __launch_bounds__(TPB, CTAS_PER_SM)
bfm_kernel(const float* __restrict__ x,
           const float* __restrict__ wb,
           const float* __restrict__ w0,
           const float* __restrict__ delta,
           const float* __restrict__ uV,
           const float* __restrict__ tV,
           const float* __restrict__ bV,
           float* __restrict__ out,
           int out_size, int P4, int P, int N, int M, int nscan, int full0)
{
    const int tid = threadIdx.x;

    if ((int)blockIdx.x < nscan) {
        // ================= producer: scan =================
        const int stride = nscan * TPB;
        const int i0 = blockIdx.x * TPB + tid;
        const int i1 = i0 + stride;

        float4 a, b;
        bool ok0 = full0 | (i0 < P4);             // full0: first slot always in range
        bool ok1 = i1 < P4;
        if (ok0) a = reinterpret_cast<const float4*>(x)[i0];
        if (ok1) b = reinterpret_cast<const float4*>(x)[i1];

        if (ok0 && ((a.x != 0.f) | (a.y != 0.f) | (a.z != 0.f) | (a.w != 0.f))) {
            int base = i0 * 4;
            if (a.x != 0.f) emit_nz(base + 0, a.x, wb);
            if (a.y != 0.f) emit_nz(base + 1, a.y, wb);
            if (a.z != 0.f) emit_nz(base + 2, a.z, wb);
            if (a.w != 0.f) emit_nz(base + 3, a.w, wb);
        }
        if (ok1 && ((b.x != 0.f) | (b.y != 0.f) | (b.z != 0.f) | (b.w != 0.f))) {
            int base = i1 * 4;
            if (b.x != 0.f) emit_nz(base + 0, b.x, wb);
            if (b.y != 0.f) emit_nz(base + 1, b.y, wb);
            if (b.z != 0.f) emit_nz(base + 2, b.z, wb);
            if (b.w != 0.f) emit_nz(base + 3, b.w, wb);
        }
        if (blockIdx.x == 0 && tid == 0) {        // tail (P not multiple of 4)
            for (int r = P4 * 4; r < P; ++r) {
                float v = x[r];
                if (v != 0.f) emit_nz(r, v, wb);
            }
        }

        __syncthreads();                          // block-scope order of emits
        if (tid == 0) {
            __threadfence();                      // cumulative release to gpu scope
            atomicAdd(&g_done, 1);
        }
        return;
    }

    // ================= consumer: streaming gather =================
    __shared__ float sA[TPB], sB[TPB], sC[TPB], sD[TPB];
    __shared__ float s_warp[2];

    const int k  = tid & (KDIM - 1);
    const int g8 = tid >> 6;                      // group 0..7, handles j % 8 == g8
    float au = 0.f, at_ = 0.f, ab = 0.f, absq = 0.f;

    int j = g8;
    for (;;) {
        unsigned long long packed =
            *(volatile const unsigned long long*)(g_pair + j);
        if (packed == 0ULL) {
            if (*(volatile const int*)&g_done == nscan) {
                __threadfence();                  // acquire: emits + nnz visible
                int final_nnz = *(volatile const int*)&g_nnz;
                if (j >= final_nnz) break;        // group exhausted
                continue;                         // entry exists; poll until visible
            }
            continue;                             // still producing
        }
        int   idx = (int)(packed >> 32);
        float v   = __uint_as_float((unsigned int)packed);
        bool isU = idx < N;
        bool isT = !isU && (idx < N + M);
        bool isB = !isU && !isT;
        const float* p = isU ? (uV + (size_t)idx * KDIM)
                       : isT ? (tV + (size_t)(idx - N) * KDIM)
                             : (bV + (size_t)(idx - N - M) * KDIM);
        float e  = p[k];
        float ve = v * e;
        au   += isU ? ve : 0.f;
        at_  += isT ? ve : 0.f;
        ab   += isB ? ve : 0.f;
        absq += isB ? ve * e : 0.f;
        j += 8;
    }

    sA[tid] = au; sB[tid] = at_; sC[tid] = ab; sD[tid] = absq;

    // reset consumed pairs for next graph replay (before barrier; each group
    // clears exactly the entries it consumed, so no overlap)
    {
        const int nnz_local = j;                  // first unconsumed for this group
        for (int q = g8 + ((tid & 63) >> 6); q < nnz_local; q += 8)
            if ((q & 7) == g8 && (tid & 63) == 0) g_pair[q] = 0ULL;
    }
    __syncthreads();                              // barrier 1

    if (tid < KDIM) {
        float u = 0.f, t = 0.f, bb = 0.f, aq = 0.f;
        #pragma unroll
        for (int q = 0; q < 8; ++q) {
            u  += sA[tid + 64 * q];
            t  += sB[tid + 64 * q];
            bb += sC[tid + 64 * q];
            aq += sD[tid + 64 * q];
        }
        float lane = u * t + t * bb + u * bb + 0.5f * bb * bb - 0.5f * aq;
        #pragma unroll
        for (int off = 16; off > 0; off >>= 1)
            lane += __shfl_down_sync(0xffffffffu, lane, off);
        if ((tid & 31) == 0) s_warp[tid >> 5] = lane;
    }
    __syncthreads();                              // barrier 2

    if (tid == 0) {
        float y = w0[0] + g_bias + s_warp[0] + s_warp[1];
        float z = y * delta[0];
        float r = 1.f / (1.f + expf(-z));
        for (int q = 0; q < out_size; ++q) out[q] = r;
        g_nnz = 0; g_done = 0; g_bias = 0.f;
    }
}

extern "C" void kernel_launch(void* const* d_in, const int* in_sizes, int n_in,
                              void* d_out, int out_size)
{
    const float* x     = (const float*)d_in[0];
    const float* delta = (const float*)d_in[1];
    /* pmi = d_in[2] unused */
    const float* w0    = (const float*)d_in[3];
    const float* wb    = (const float*)d_in[4];
    const float* uV    = (const float*)d_in[5];
    const float* tV    = (const float*)d_in[6];
    const float* bV    = (const float*)d_in[7];

    int P  = in_sizes[0];
    int N  = in_sizes[5] / KDIM;
    int M  = in_sizes[6] / KDIM;
    int P4 = P / 4;

    int blocks = NSM * CTAS_PER_SM;               // single wave (incl. consumer)
    int nscan  = blocks - 1;
    int needed = (P4 + 2 * TPB - 1) / (2 * TPB);  // producer coverage (2 f4/thread)
    if (nscan < needed) { nscan = needed; blocks = nscan + 1; }
    int full0 = (nscan * TPB <= P4) ? 1 : 0;      // first slot always in range?

    bfm_kernel<<<blocks, TPB>>>(x, wb, w0, delta, uV, tV, bV,
                                (float*)d_out, out_size, P4, P, N, M, nscan, full0);
}

// round 12
// speedup vs baseline: 1.1594x; 1.1594x over previous
#include <cuda_runtime.h>
#include <math.h>

// ---------------------------------------------------------------------------
// BFM factorization-machine scoring, sparsity-aware, single fused kernel with
// a dedicated streaming-consumer block (pipelined poll).
//   y = w0 + x.w_bias + u.t + t.b + 0.5*(b.b - sum_b_sq) + u.b
//   out = sigmoid(y * delta)
// 591 producer blocks scan x (2 float4/thread) and publish packed (idx,val)
// pairs via atomicExch; bias accumulates via rare scalar atomics. Block
// gridDim-1 is a consumer: its 8 thread-groups poll the pair list with a
// one-slot prefetch pipeline and gather embedding rows WHILE the scan runs.
// ---------------------------------------------------------------------------

#define KDIM 64
#define TPB  512
#define CTAS_PER_SM 4
#define NSM  148
#define PAIR_CAP 4352   // 4096 usable + prefetch headroom

__device__ int                g_nnz  = 0;
__device__ int                g_done = 0;
__device__ float              g_bias = 0.f;
__device__ unsigned long long g_pair[PAIR_CAP];   // (idx<<32)|bits(val); 0 = empty

__device__ __forceinline__ void emit_nz(int idx, float v, const float* __restrict__ wb)
{
    int p = atomicAdd(&g_nnz, 1);
    unsigned long long packed =
        ((unsigned long long)(unsigned int)idx << 32) | (unsigned long long)__float_as_uint(v);
    atomicExch(&g_pair[p], packed);               // strong write, poll-visible
    atomicAdd(&g_bias, v * __ldg(wb + idx));
}

__global__ void __launch_bounds__(TPB, CTAS_PER_SM)
bfm_kernel(const float* __restrict__ x,
           const float* __restrict__ wb,
           const float* __restrict__ w0,
           const float* __restrict__ delta,
           const float* __restrict__ uV,
           const float* __restrict__ tV,
           const float* __restrict__ bV,
           float* __restrict__ out,
           int out_size, int P4, int P, int N, int M, int nscan, int full0)
{
    const int tid = threadIdx.x;

    if ((int)blockIdx.x < nscan) {
        // ================= producer: scan =================
        const int stride = nscan * TPB;
        const int i0 = blockIdx.x * TPB + tid;
        const int i1 = i0 + stride;

        float4 a, b;
        bool ok0 = full0 | (i0 < P4);
        bool ok1 = i1 < P4;
        if (ok0) a = reinterpret_cast<const float4*>(x)[i0];
        if (ok1) b = reinterpret_cast<const float4*>(x)[i1];

        if (ok0 && ((a.x != 0.f) | (a.y != 0.f) | (a.z != 0.f) | (a.w != 0.f))) {
            int base = i0 * 4;
            if (a.x != 0.f) emit_nz(base + 0, a.x, wb);
            if (a.y != 0.f) emit_nz(base + 1, a.y, wb);
            if (a.z != 0.f) emit_nz(base + 2, a.z, wb);
            if (a.w != 0.f) emit_nz(base + 3, a.w, wb);
        }
        if (ok1 && ((b.x != 0.f) | (b.y != 0.f) | (b.z != 0.f) | (b.w != 0.f))) {
            int base = i1 * 4;
            if (b.x != 0.f) emit_nz(base + 0, b.x, wb);
            if (b.y != 0.f) emit_nz(base + 1, b.y, wb);
            if (b.z != 0.f) emit_nz(base + 2, b.z, wb);
            if (b.w != 0.f) emit_nz(base + 3, b.w, wb);
        }
        if (blockIdx.x == 0 && tid == 0) {        // tail (P not multiple of 4)
            for (int r = P4 * 4; r < P; ++r) {
                float v = x[r];
                if (v != 0.f) emit_nz(r, v, wb);
            }
        }

        __syncthreads();
        if (tid == 0) {
            __threadfence();                      // release emits before done
            atomicAdd(&g_done, 1);
        }
        return;
    }

    // ================= consumer: streaming gather, pipelined poll ==========
    __shared__ float sA[TPB], sB[TPB], sC[TPB], sD[TPB];
    __shared__ float s_warp[2];

    const int k  = tid & (KDIM - 1);
    const int g8 = tid >> 6;                      // group 0..7, handles j % 8 == g8
    float au = 0.f, at_ = 0.f, ab = 0.f, absq = 0.f;

    int j = g8;
    unsigned long long cur = *(volatile const unsigned long long*)(g_pair + j);
    for (;;) {
        if (cur == 0ULL) {
            if (*(volatile const int*)&g_done == nscan) {
                __threadfence();                  // acquire: emits + nnz visible
                int final_nnz = *(volatile const int*)&g_nnz;
                if (j >= final_nnz) break;        // group exhausted
            }
            cur = *(volatile const unsigned long long*)(g_pair + j);
            continue;
        }
        // prefetch next slot for this group BEFORE processing current entry:
        // its L2 round-trip overlaps the embedding-row load below.
        unsigned long long pf = *(volatile const unsigned long long*)(g_pair + j + 8);

        int   idx = (int)(cur >> 32);
        float v   = __uint_as_float((unsigned int)cur);
        bool isU = idx < N;
        bool isT = !isU && (idx < N + M);
        bool isB = !isU && !isT;
        const float* p = isU ? (uV + (size_t)idx * KDIM)
                       : isT ? (tV + (size_t)(idx - N) * KDIM)
                             : (bV + (size_t)(idx - N - M) * KDIM);
        float e  = p[k];
        float ve = v * e;
        au   += isU ? ve : 0.f;
        at_  += isT ? ve : 0.f;
        ab   += isB ? ve : 0.f;
        absq += isB ? ve * e : 0.f;

        j += 8;
        cur = pf;
    }

    sA[tid] = au; sB[tid] = at_; sC[tid] = ab; sD[tid] = absq;

    // reset consumed pairs for next graph replay: one lane per group clears
    // exactly the slots its group consumed (j = first unconsumed, group-uniform)
    if ((tid & 63) == 0) {
        for (int q = g8; q < j; q += 8) g_pair[q] = 0ULL;
    }
    __syncthreads();                              // barrier 1

    if (tid < KDIM) {
        float u = 0.f, t = 0.f, bb = 0.f, aq = 0.f;
        #pragma unroll
        for (int q = 0; q < 8; ++q) {
            u  += sA[tid + 64 * q];
            t  += sB[tid + 64 * q];
            bb += sC[tid + 64 * q];
            aq += sD[tid + 64 * q];
        }
        float lane = u * t + t * bb + u * bb + 0.5f * bb * bb - 0.5f * aq;
        #pragma unroll
        for (int off = 16; off > 0; off >>= 1)
            lane += __shfl_down_sync(0xffffffffu, lane, off);
        if ((tid & 31) == 0) s_warp[tid >> 5] = lane;
    }
    __syncthreads();                              // barrier 2

    if (tid == 0) {
        float y = w0[0] + g_bias + s_warp[0] + s_warp[1];
        float z = y * delta[0];
        float r = 1.f / (1.f + expf(-z));
        for (int q = 0; q < out_size; ++q) out[q] = r;
        g_nnz = 0; g_done = 0; g_bias = 0.f;
    }
}

extern "C" void kernel_launch(void* const* d_in, const int* in_sizes, int n_in,
                              void* d_out, int out_size)
{
    const float* x     = (const float*)d_in[0];
    const float* delta = (const float*)d_in[1];
    /* pmi = d_in[2] unused */
    const float* w0    = (const float*)d_in[3];
    const float* wb    = (const float*)d_in[4];
    const float* uV    = (const float*)d_in[5];
    const float* tV    = (const float*)d_in[6];
    const float* bV    = (const float*)d_in[7];

    int P  = in_sizes[0];
    int N  = in_sizes[5] / KDIM;
    int M  = in_sizes[6] / KDIM;
    int P4 = P / 4;

    int blocks = NSM * CTAS_PER_SM;               // single wave (incl. consumer)
    int nscan  = blocks - 1;
    int needed = (P4 + 2 * TPB - 1) / (2 * TPB);  // producer coverage (2 f4/thread)
    if (nscan < needed) { nscan = needed; blocks = nscan + 1; }
    int full0 = (nscan * TPB <= P4) ? 1 : 0;      // first slot always in range?

    bfm_kernel<<<blocks, TPB>>>(x, wb, w0, delta, uV, tV, bV,
                                (float*)d_out, out_size, P4, P, N, M, nscan, full0);
}

// round 13
// speedup vs baseline: 1.1940x; 1.0299x over previous
#include <cuda_runtime.h>
#include <math.h>

// ---------------------------------------------------------------------------
// BFM factorization-machine scoring, sparsity-aware, single fused kernel with
// a dedicated streaming-consumer block (pipelined poll, hierarchical done).
//   y = w0 + x.w_bias + u.t + t.b + 0.5*(b.b - sum_b_sq) + u.b
//   out = sigmoid(y * delta)
// Producer blocks (blockIdx 1..nscan) scan x (2 float4/thread) and publish
// packed (idx,val) pairs; bias accumulates via rare scalar atomics. Block 0
// is a consumer: its 8 thread-groups poll the pair list with a one-slot
// prefetch pipeline and gather embedding rows WHILE the scan runs. Done
// signaling uses 8 padded counters to avoid single-address LTS serialization.
// ---------------------------------------------------------------------------

#define KDIM 64
#define TPB  512
#define CTAS_PER_SM 4
#define NSM  148
#define PAIR_CAP 4352   // 4096 usable + prefetch headroom

__device__ int                g_nnz  = 0;
__device__ float              g_bias = 0.f;
__device__ int                g_done[8 * 32];    // 8 counters, 128B apart
__device__ unsigned long long g_pair[PAIR_CAP];  // (idx<<32)|bits(val); 0 = empty

__device__ __forceinline__ void emit_nz(int idx, float v, const float* __restrict__ wb)
{
    int p = atomicAdd(&g_nnz, 1);
    unsigned long long packed =
        ((unsigned long long)(unsigned int)idx << 32) | (unsigned long long)__float_as_uint(v);
    *(volatile unsigned long long*)(g_pair + p) = packed;  // L2-coherent store
    atomicAdd(&g_bias, v * __ldg(wb + idx));
}

__global__ void __launch_bounds__(TPB, CTAS_PER_SM)
bfm_kernel(const float* __restrict__ x,
           const float* __restrict__ wb,
           const float* __restrict__ w0,
           const float* __restrict__ delta,
           const float* __restrict__ uV,
           const float* __restrict__ tV,
           const float* __restrict__ bV,
           float* __restrict__ out,
           int out_size, int P4, int P, int N, int M, int nscan, int full0)
{
    const int tid = threadIdx.x;

    if (blockIdx.x != 0) {
        // ================= producer: scan =================
        const int pb = (int)blockIdx.x - 1;        // producer rank 0..nscan-1
        const int stride = nscan * TPB;
        const int i0 = pb * TPB + tid;
        const int i1 = i0 + stride;

        float4 a, b;
        bool ok0 = full0 | (i0 < P4);
        bool ok1 = i1 < P4;
        if (ok0) a = reinterpret_cast<const float4*>(x)[i0];
        if (ok1) b = reinterpret_cast<const float4*>(x)[i1];

        if (ok0 && ((a.x != 0.f) | (a.y != 0.f) | (a.z != 0.f) | (a.w != 0.f))) {
            int base = i0 * 4;
            if (a.x != 0.f) emit_nz(base + 0, a.x, wb);
            if (a.y != 0.f) emit_nz(base + 1, a.y, wb);
            if (a.z != 0.f) emit_nz(base + 2, a.z, wb);
            if (a.w != 0.f) emit_nz(base + 3, a.w, wb);
        }
        if (ok1 && ((b.x != 0.f) | (b.y != 0.f) | (b.z != 0.f) | (b.w != 0.f))) {
            int base = i1 * 4;
            if (b.x != 0.f) emit_nz(base + 0, b.x, wb);
            if (b.y != 0.f) emit_nz(base + 1, b.y, wb);
            if (b.z != 0.f) emit_nz(base + 2, b.z, wb);
            if (b.w != 0.f) emit_nz(base + 3, b.w, wb);
        }
        if (pb == 0 && tid == 0) {                 // tail (P not multiple of 4)
            for (int r = P4 * 4; r < P; ++r) {
                float v = x[r];
                if (v != 0.f) emit_nz(r, v, wb);
            }
        }

        __syncthreads();
        if (tid == 0) {
            __threadfence();                       // release emits before done
            atomicAdd(&g_done[(pb & 7) * 32], 1);  // 8-way spread counters
        }
        return;
    }

    // ================= consumer (block 0): streaming gather ================
    __shared__ float sA[TPB], sB[TPB], sC[TPB], sD[TPB];
    __shared__ float s_warp[2];

    const int k  = tid & (KDIM - 1);
    const int g8 = tid >> 6;                       // group 0..7, handles j % 8 == g8
    float au = 0.f, at_ = 0.f, ab = 0.f, absq = 0.f;

    int j = g8;
    unsigned long long cur = *(volatile const unsigned long long*)(g_pair + j);
    for (;;) {
        if (cur == 0ULL) {
            int dsum = 0;
            #pragma unroll
            for (int q = 0; q < 8; ++q) dsum += *(volatile const int*)&g_done[q * 32];
            if (dsum == nscan) {
                __threadfence();                   // acquire: emits + nnz visible
                int final_nnz = *(volatile const int*)&g_nnz;
                if (j >= final_nnz) break;         // group exhausted
            }
            cur = *(volatile const unsigned long long*)(g_pair + j);
            continue;
        }
        // prefetch next slot: its L2 round-trip overlaps the row load below
        unsigned long long pf = *(volatile const unsigned long long*)(g_pair + j + 8);

        int   idx = (int)(cur >> 32);
        float v   = __uint_as_float((unsigned int)cur);
        bool isU = idx < N;
        bool isT = !isU && (idx < N + M);
        bool isB = !isU && !isT;
        const float* p = isU ? (uV + (size_t)idx * KDIM)
                       : isT ? (tV + (size_t)(idx - N) * KDIM)
                             : (bV + (size_t)(idx - N - M) * KDIM);
        float e  = p[k];
        float ve = v * e;
        au   += isU ? ve : 0.f;
        at_  += isT ? ve : 0.f;
        ab   += isB ? ve : 0.f;
        absq += isB ? ve * e : 0.f;

        j += 8;
        cur = pf;
    }

    sA[tid] = au; sB[tid] = at_; sC[tid] = ab; sD[tid] = absq;

    // reset consumed pairs for next graph replay (one lane per group)
    if ((tid & 63) == 0) {
        for (int q = g8; q < j; q += 8) g_pair[q] = 0ULL;
    }
    __syncthreads();                               // barrier 1

    if (tid < KDIM) {
        float u = 0.f, t = 0.f, bb = 0.f, aq = 0.f;
        #pragma unroll
        for (int q = 0; q < 8; ++q) {
            u  += sA[tid + 64 * q];
            t  += sB[tid + 64 * q];
            bb += sC[tid + 64 * q];
            aq += sD[tid + 64 * q];
        }
        float lane = u * t + t * bb + u * bb + 0.5f * bb * bb - 0.5f * aq;
        #pragma unroll
        for (int off = 16; off > 0; off >>= 1)
            lane += __shfl_down_sync(0xffffffffu, lane, off);
        if ((tid & 31) == 0) s_warp[tid >> 5] = lane;
    }
    __syncthreads();                               // barrier 2

    if (tid == 0) {
        float y = w0[0] + g_bias + s_warp[0] + s_warp[1];
        float z = y * delta[0];
        float r = 1.f / (1.f + expf(-z));
        for (int q = 0; q < out_size; ++q) out[q] = r;
        g_nnz = 0; g_bias = 0.f;
        #pragma unroll
        for (int q = 0; q < 8; ++q) g_done[q * 32] = 0;
    }
}

extern "C" void kernel_launch(void* const* d_in, const int* in_sizes, int n_in,
                              void* d_out, int out_size)
{
    const float* x     = (const float*)d_in[0];
    const float* delta = (const float*)d_in[1];
    /* pmi = d_in[2] unused */
    const float* w0    = (const float*)d_in[3];
    const float* wb    = (const float*)d_in[4];
    const float* uV    = (const float*)d_in[5];
    const float* tV    = (const float*)d_in[6];
    const float* bV    = (const float*)d_in[7];

    int P  = in_sizes[0];
    int N  = in_sizes[5] / KDIM;
    int M  = in_sizes[6] / KDIM;
    int P4 = P / 4;

    int blocks = NSM * CTAS_PER_SM;                // single wave (incl. consumer)
    int nscan  = blocks - 1;
    int needed = (P4 + 2 * TPB - 1) / (2 * TPB);   // producer coverage (2 f4/thread)
    if (nscan < needed) { nscan = needed; blocks = nscan + 1; }
    int full0 = (nscan * TPB <= P4) ? 1 : 0;       // first slot always in range?

    bfm_kernel<<<blocks, TPB>>>(x, wb, w0, delta, uV, tV, bV,
                                (float*)d_out, out_size, P4, P, N, M, nscan, full0);
}